// round 15
// baseline (speedup 1.0000x reference)
#include <cuda_runtime.h>
#include <cuda_bf16.h>
#include <math.h>

// ---------------------------------------------------------------------------
// CriticRNN: T=128, B=128, OBS=512, H=1024
// GEMMs + GRU scan via tf32 mma.sync (3xtf32 split).
// NEW: xi GEMM split into 8 time-chunks on a forked stream, overlapped with
// the persistent scan via device flags (scan polls xiflag[t/16]).
// ---------------------------------------------------------------------------

#define TT  128
#define BB  128
#define OBS 512
#define HH  1024
#define H3  3072
#define MM  (TT * BB)   // 16384
#define COLG 32         // h-column groups (32 cols each)
#define KQ   4          // K split factor in the scan
#define KS   (HH / KQ)  // 256 k per split
#define NCHUNK 8        // xi time chunks (16 steps each)

// Static device scratch (no allocations allowed)
__device__ float    g_emb[(size_t)MM * HH];      // 64 MB
__device__ float    g_xi[(size_t)MM * H3];       // 192 MB
__device__ float    g_y[(size_t)MM * HH];        // 64 MB
__device__ float    g_critic[(size_t)MM * HH];   // 64 MB
__device__ unsigned g_whh[(size_t)HH * H3];      // 12.6 MB  Wh hi (tf32)
__device__ unsigned g_whl[(size_t)HH * H3];      // 12.6 MB  Wh lo (tf32)
__device__ unsigned g_wembh[(size_t)OBS * HH];   // 2.1 MB   W_emb hi
__device__ unsigned g_wembl[(size_t)OBS * HH];   // 2.1 MB   W_emb lo
__device__ unsigned g_wih[(size_t)HH * H3];      // 12.6 MB  Wi hi
__device__ unsigned g_wil[(size_t)HH * H3];      // 12.6 MB  Wi lo
__device__ unsigned g_w1h[(size_t)HH * HH];      // 4.2 MB   W1 hi
__device__ unsigned g_w1l[(size_t)HH * HH];      // 4.2 MB   W1 lo
__device__ unsigned g_hh[BB * HH];               // masked h hi
__device__ unsigned g_hl[BB * HH];               // masked h lo
__device__ float    g_hf[BB * HH];               // masked h fp32
__device__ float    g_part[(size_t)KQ * COLG * BB * 96];  // 6.3 MB partials
__device__ float    g_mask[MM];
__device__ int      g_bytemode;
__device__ unsigned g_bars[8 * 32];              // striped barrier counters
__device__ int      g_xiflag[NCHUNK];            // xi chunk-ready flags

// ---------------------------------------------------------------------------
// dones layout detection + mask expansion (byte-bool vs int32).
// ---------------------------------------------------------------------------
__global__ void detect_mask_mode(const unsigned int* __restrict__ d)
{
    __shared__ int flag;
    if (threadIdx.x == 0) flag = 0;
    __syncthreads();
    int f = 0;
    for (int i = threadIdx.x; i < MM / 4; i += blockDim.x)
        if (d[i] > 1u) f = 1;
    if (f) atomicOr(&flag, 1);
    __syncthreads();
    if (threadIdx.x == 0) g_bytemode = flag;
}

__global__ void expand_mask(const void* __restrict__ dones, float* __restrict__ mask)
{
    const int i = blockIdx.x * blockDim.x + threadIdx.x;
    if (i >= MM) return;
    int done;
    if (g_bytemode)
        done = ((const unsigned char*)dones)[i] != 0;
    else
        done = ((const int*)dones)[i] != 0;
    mask[i] = done ? 0.f : 1.f;
}

// ---------------------------------------------------------------------------
// tf32 helpers
// ---------------------------------------------------------------------------
__device__ __forceinline__ unsigned f2tf(float x)
{
    unsigned u;
    asm("cvt.rna.tf32.f32 %0, %1;" : "=r"(u) : "f"(x));
    return u;
}
__device__ __forceinline__ void tf_split(float x, unsigned& hi, unsigned& lo)
{
    hi = f2tf(x);
    lo = f2tf(x - __uint_as_float(hi));
}
__device__ __forceinline__ void mma_tf32(float* d,
                                         unsigned a0, unsigned a1, unsigned a2, unsigned a3,
                                         unsigned b0, unsigned b1)
{
    asm("mma.sync.aligned.m16n8k8.row.col.f32.tf32.tf32.f32 "
        "{%0,%1,%2,%3}, {%4,%5,%6,%7}, {%8,%9}, {%0,%1,%2,%3};"
        : "+f"(d[0]), "+f"(d[1]), "+f"(d[2]), "+f"(d[3])
        : "r"(a0), "r"(a1), "r"(a2), "r"(a3), "r"(b0), "r"(b1));
}

// ---------------------------------------------------------------------------
// Prep kernels
// ---------------------------------------------------------------------------
__global__ void split_mat(const float* __restrict__ src,
                          unsigned* __restrict__ hi_out,
                          unsigned* __restrict__ lo_out, int n)
{
    const int i = blockIdx.x * blockDim.x + threadIdx.x;
    if (i >= n) return;
    unsigned hi, lo;
    tf_split(src[i], hi, lo);
    hi_out[i] = hi;
    lo_out[i] = lo;
}

__global__ void init_h(const float* __restrict__ hidden, const float* __restrict__ mask)
{
    const int i = blockIdx.x * blockDim.x + threadIdx.x;
    if (i >= BB * HH) return;
    const float v = hidden[i] * mask[i / HH];
    g_hf[i] = v;
    unsigned hi, lo;
    tf_split(v, hi, lo);
    g_hh[i] = hi;
    g_hl[i] = lo;
}

__global__ void set_flag(int idx)
{
    atomicExch(&g_xiflag[idx], 1);
}

// ---------------------------------------------------------------------------
// tf32 3x-split tensor-core GEMM, double-buffered, pre-split B:
//   C = op(A@B + bias),  B given as tf32 hi/lo planes. 2 blocks/SM.
// ---------------------------------------------------------------------------
#define PAD 136

template <int DO_RELU>
__global__ __launch_bounds__(256, 2)
void mma_gemm(const float* __restrict__ A,
              const unsigned* __restrict__ Bhg, const unsigned* __restrict__ Blg,
              const float* __restrict__ bias, float* __restrict__ C,
              int M, int N, int K)
{
    __shared__ unsigned Ah[2][8][PAD];
    __shared__ unsigned Al[2][8][PAD];
    __shared__ unsigned Bh[2][8][PAD];
    __shared__ unsigned Bl[2][8][PAD];

    const int tid  = threadIdx.x;
    const int wid  = tid >> 5;
    const int lane = tid & 31;
    const int gid  = lane >> 2;
    const int tig  = lane & 3;

    const int cRow = blockIdx.y * 128;
    const int cCol = blockIdx.x * 128;

    const int warp_m = (wid >> 2) * 64;
    const int warp_n = (wid & 3) * 32;

    const int arow = tid >> 1;
    const int acol = (tid & 1) * 4;
    const float* Ap = A + (size_t)(cRow + arow) * K + acol;

    const int bkrow = tid >> 5;
    const int bcol  = (tid & 31) * 4;
    const unsigned* Bph = Bhg + (size_t)bkrow * N + cCol + bcol;
    const unsigned* Bpl = Blg + (size_t)bkrow * N + cCol + bcol;

    float acc[4][4][4];
    #pragma unroll
    for (int i = 0; i < 4; i++)
        #pragma unroll
        for (int j = 0; j < 4; j++)
            #pragma unroll
            for (int r = 0; r < 4; r++) acc[i][j][r] = 0.f;

    float4 a4 = *(const float4*)(Ap);
    uint4 bh4 = *(const uint4*)(Bph);
    uint4 bl4 = *(const uint4*)(Bpl);
    {
        float av[4] = {a4.x, a4.y, a4.z, a4.w};
        #pragma unroll
        for (int c = 0; c < 4; c++) {
            unsigned hi, lo;
            tf_split(av[c], hi, lo);
            Ah[0][acol + c][arow] = hi;
            Al[0][acol + c][arow] = lo;
        }
        *(uint4*)&Bh[0][bkrow][bcol] = bh4;
        *(uint4*)&Bl[0][bkrow][bcol] = bl4;
    }
    __syncthreads();

    int buf = 0;
    for (int kb = 0; kb < K; kb += 8) {
        const bool more = (kb + 8) < K;
        if (more) {
            a4  = *(const float4*)(Ap + kb + 8);
            bh4 = *(const uint4*)(Bph + (size_t)(kb + 8) * N);
            bl4 = *(const uint4*)(Bpl + (size_t)(kb + 8) * N);
        }

        {
            unsigned bh[4][2], bl[4][2];
            #pragma unroll
            for (int j = 0; j < 4; j++) {
                const int n0 = warp_n + j * 8 + gid;
                bh[j][0] = Bh[buf][tig][n0];
                bh[j][1] = Bh[buf][tig + 4][n0];
                bl[j][0] = Bl[buf][tig][n0];
                bl[j][1] = Bl[buf][tig + 4][n0];
            }
            #pragma unroll
            for (int i = 0; i < 4; i++) {
                const int r0 = warp_m + i * 16 + gid;
                const unsigned ah0 = Ah[buf][tig][r0];
                const unsigned ah1 = Ah[buf][tig][r0 + 8];
                const unsigned ah2 = Ah[buf][tig + 4][r0];
                const unsigned ah3 = Ah[buf][tig + 4][r0 + 8];
                const unsigned al0 = Al[buf][tig][r0];
                const unsigned al1 = Al[buf][tig][r0 + 8];
                const unsigned al2 = Al[buf][tig + 4][r0];
                const unsigned al3 = Al[buf][tig + 4][r0 + 8];
                #pragma unroll
                for (int j = 0; j < 4; j++) {
                    mma_tf32(acc[i][j], ah0, ah1, ah2, ah3, bh[j][0], bh[j][1]);
                    mma_tf32(acc[i][j], ah0, ah1, ah2, ah3, bl[j][0], bl[j][1]);
                    mma_tf32(acc[i][j], al0, al1, al2, al3, bh[j][0], bh[j][1]);
                }
            }
        }

        if (more) {
            const int nb = buf ^ 1;
            float av[4] = {a4.x, a4.y, a4.z, a4.w};
            #pragma unroll
            for (int c = 0; c < 4; c++) {
                unsigned hi, lo;
                tf_split(av[c], hi, lo);
                Ah[nb][acol + c][arow] = hi;
                Al[nb][acol + c][arow] = lo;
            }
            *(uint4*)&Bh[nb][bkrow][bcol] = bh4;
            *(uint4*)&Bl[nb][bkrow][bcol] = bl4;
        }
        __syncthreads();
        buf ^= 1;
    }

    #pragma unroll
    for (int i = 0; i < 4; i++) {
        const int row0 = cRow + warp_m + i * 16 + gid;
        #pragma unroll
        for (int j = 0; j < 4; j++) {
            const int col = cCol + warp_n + j * 8 + tig * 2;
            float2 v0, v1;
            v0.x = acc[i][j][0] + bias[col];
            v0.y = acc[i][j][1] + bias[col + 1];
            v1.x = acc[i][j][2] + bias[col];
            v1.y = acc[i][j][3] + bias[col + 1];
            if (DO_RELU) {
                v0.x = fmaxf(v0.x, 0.f); v0.y = fmaxf(v0.y, 0.f);
                v1.x = fmaxf(v1.x, 0.f); v1.y = fmaxf(v1.y, 0.f);
            }
            *(float2*)&C[(size_t)row0 * N + col]       = v0;
            *(float2*)&C[(size_t)(row0 + 8) * N + col] = v1;
        }
    }
}

// ---------------------------------------------------------------------------
// Persistent tensor-core GRU scan (R11-best structure, regs capped to 128
// for co-residency with the concurrent xi chunk GEMMs). Polls g_xiflag[t/16]
// before consuming xi in phase 2.
// ---------------------------------------------------------------------------
__global__ __launch_bounds__(256, 2)
void gru_scan_mma(const float* __restrict__ mask,
                  const float* __restrict__ xi,
                  const float* __restrict__ bhn,
                  float* __restrict__ y)
{
    __shared__ unsigned Ah[2][8][136];
    __shared__ unsigned Al[2][8][136];
    __shared__ unsigned Bh[2][8][104];
    __shared__ unsigned Bl[2][8][104];

    const int tid  = threadIdx.x;
    const int wid  = tid >> 5;
    const int lane = tid & 31;
    const int gid  = lane >> 2;
    const int tig  = lane & 3;

    const int c = blockIdx.x;        // colgroup 0..31
    const int q = blockIdx.y;        // k-quarter 0..3
    const int bn32  = c * 32;
    const int kbase = q * KS;
    const int bid   = q * COLG + c;

    const int warp_m = (wid >> 2) * 64;   // 0 / 64
    const int warp_n = (wid & 3) * 24;    // 0,24,48,72

    const int arow = tid >> 1;
    const int acol = (tid & 1) * 4;
    const unsigned* hhp = g_hh + (size_t)arow * HH + kbase + acol;
    const unsigned* hlp = g_hl + (size_t)arow * HH + kbase + acol;

    const bool bv = (tid < 192);
    const int kr = tid / 24, c4 = tid % 24;
    const int bn0 = (c4 >> 3) * 32 + (c4 & 7) * 4;
    const size_t boff = (size_t)(kbase + kr) * H3 + (c4 >> 3) * HH + bn32 + (c4 & 7) * 4;

    float* partp = g_part + (size_t)(q * COLG + c) * BB * 96;

    const int rloc = tid >> 3;
    const int jj   = (tid & 7) * 4;
    const int pb   = q * 32 + rloc;
    const int pj   = bn32 + jj;

    unsigned tgt = 0;

    for (int t = 0; t < TT; t++) {
        // ================= phase 1: mma partials =================
        float acc[4][3][4];
        #pragma unroll
        for (int i = 0; i < 4; i++)
            #pragma unroll
            for (int j = 0; j < 3; j++)
                #pragma unroll
                for (int r = 0; r < 4; r++) acc[i][j][r] = 0.f;

        uint4 pah = *(const uint4*)(hhp);
        uint4 pal = *(const uint4*)(hlp);
        uint4 pbh = bv ? *(const uint4*)(g_whh + boff) : make_uint4(0, 0, 0, 0);
        uint4 pbl = bv ? *(const uint4*)(g_whl + boff) : make_uint4(0, 0, 0, 0);

        {
            Ah[0][acol + 0][arow] = pah.x;
            Ah[0][acol + 1][arow] = pah.y;
            Ah[0][acol + 2][arow] = pah.z;
            Ah[0][acol + 3][arow] = pah.w;
            Al[0][acol + 0][arow] = pal.x;
            Al[0][acol + 1][arow] = pal.y;
            Al[0][acol + 2][arow] = pal.z;
            Al[0][acol + 3][arow] = pal.w;
            if (bv) {
                *(uint4*)&Bh[0][kr][bn0] = pbh;
                *(uint4*)&Bl[0][kr][bn0] = pbl;
            }
        }
        __syncthreads();

        int buf = 0;
        #pragma unroll 1
        for (int kb = 0; kb < KS; kb += 8) {
            const bool more = (kb + 8) < KS;
            if (more) {
                pah = *(const uint4*)(hhp + kb + 8);
                pal = *(const uint4*)(hlp + kb + 8);
                if (bv) {
                    pbh = *(const uint4*)(g_whh + boff + (size_t)(kb + 8) * H3);
                    pbl = *(const uint4*)(g_whl + boff + (size_t)(kb + 8) * H3);
                }
            }

            {
                unsigned bh[3][2], bl[3][2];
                #pragma unroll
                for (int j = 0; j < 3; j++) {
                    const int n0 = warp_n + j * 8 + gid;
                    bh[j][0] = Bh[buf][tig][n0];
                    bh[j][1] = Bh[buf][tig + 4][n0];
                    bl[j][0] = Bl[buf][tig][n0];
                    bl[j][1] = Bl[buf][tig + 4][n0];
                }
                #pragma unroll
                for (int i = 0; i < 4; i++) {
                    const int r0 = warp_m + i * 16 + gid;
                    const unsigned ah0 = Ah[buf][tig][r0];
                    const unsigned ah1 = Ah[buf][tig][r0 + 8];
                    const unsigned ah2 = Ah[buf][tig + 4][r0];
                    const unsigned ah3 = Ah[buf][tig + 4][r0 + 8];
                    const unsigned al0 = Al[buf][tig][r0];
                    const unsigned al1 = Al[buf][tig][r0 + 8];
                    const unsigned al2 = Al[buf][tig + 4][r0];
                    const unsigned al3 = Al[buf][tig + 4][r0 + 8];
                    #pragma unroll
                    for (int j = 0; j < 3; j++) {
                        mma_tf32(acc[i][j], ah0, ah1, ah2, ah3, bh[j][0], bh[j][1]);
                        mma_tf32(acc[i][j], ah0, ah1, ah2, ah3, bl[j][0], bl[j][1]);
                        mma_tf32(acc[i][j], al0, al1, al2, al3, bh[j][0], bh[j][1]);
                    }
                }
            }

            if (more) {
                const int nb = buf ^ 1;
                Ah[nb][acol + 0][arow] = pah.x;
                Ah[nb][acol + 1][arow] = pah.y;
                Ah[nb][acol + 2][arow] = pah.z;
                Ah[nb][acol + 3][arow] = pah.w;
                Al[nb][acol + 0][arow] = pal.x;
                Al[nb][acol + 1][arow] = pal.y;
                Al[nb][acol + 2][arow] = pal.z;
                Al[nb][acol + 3][arow] = pal.w;
                if (bv) {
                    *(uint4*)&Bh[nb][kr][bn0] = pbh;
                    *(uint4*)&Bl[nb][kr][bn0] = pbl;
                }
            }
            __syncthreads();
            buf ^= 1;
        }

        // write partials [128 x 96]
        #pragma unroll
        for (int i = 0; i < 4; i++) {
            const int row = warp_m + i * 16 + gid;
            #pragma unroll
            for (int j = 0; j < 3; j++) {
                const int col = warp_n + j * 8 + tig * 2;
                *(float2*)&partp[(size_t)row * 96 + col] =
                    make_float2(acc[i][j][0], acc[i][j][1]);
                *(float2*)&partp[(size_t)(row + 8) * 96 + col] =
                    make_float2(acc[i][j][2], acc[i][j][3]);
            }
        }

        // barrier A (striped counters) + xi chunk readiness
        tgt += 128;
        __syncthreads();
        if (tid == 0) {
            __threadfence();
            atomicAdd(&g_bars[(bid & 7) * 32], 1u);
            unsigned s;
            do {
                s = 0;
                #pragma unroll
                for (int i = 0; i < 8; i++)
                    s += *((volatile unsigned*)&g_bars[i * 32]);
            } while (s < tgt);
            // wait for xi chunk t/16 to be produced by the forked stream
            while (*((volatile int*)&g_xiflag[t >> 4]) == 0) { }
            __threadfence();
        }
        __syncthreads();

        // ================= phase 2: reduce + gates =================
        {
            float4 aR = make_float4(0.f, 0.f, 0.f, 0.f);
            float4 aZ = make_float4(0.f, 0.f, 0.f, 0.f);
            float4 aN = make_float4(0.f, 0.f, 0.f, 0.f);
            #pragma unroll
            for (int qq = 0; qq < KQ; qq++) {
                const float* pp = g_part + ((size_t)(qq * COLG + c) * BB + pb) * 96;
                float4 r4 = *(const float4*)&pp[jj];
                float4 z4 = *(const float4*)&pp[32 + jj];
                float4 n4 = *(const float4*)&pp[64 + jj];
                aR.x += r4.x; aR.y += r4.y; aR.z += r4.z; aR.w += r4.w;
                aZ.x += z4.x; aZ.y += z4.y; aZ.z += z4.z; aZ.w += z4.w;
                aN.x += n4.x; aN.y += n4.y; aN.z += n4.z; aN.w += n4.w;
            }

            const float* xi_t = xi + (size_t)t * BB * H3 + (size_t)pb * H3;
            float4 xr = *(const float4*)(xi_t + pj);
            float4 xz = *(const float4*)(xi_t + HH + pj);
            float4 xn = *(const float4*)(xi_t + 2 * HH + pj);
            float4 hp = *(const float4*)(g_hf + (size_t)pb * HH + pj);
            float4 bh = *(const float4*)(bhn + pj);

            float4 o;
            {
                const float r = 1.f / (1.f + expf(-(xr.x + aR.x)));
                const float z = 1.f / (1.f + expf(-(xz.x + aZ.x)));
                const float n = tanhf(xn.x + r * (aN.x + bh.x));
                o.x = (1.f - z) * n + z * hp.x;
            }
            {
                const float r = 1.f / (1.f + expf(-(xr.y + aR.y)));
                const float z = 1.f / (1.f + expf(-(xz.y + aZ.y)));
                const float n = tanhf(xn.y + r * (aN.y + bh.y));
                o.y = (1.f - z) * n + z * hp.y;
            }
            {
                const float r = 1.f / (1.f + expf(-(xr.z + aR.z)));
                const float z = 1.f / (1.f + expf(-(xz.z + aZ.z)));
                const float n = tanhf(xn.z + r * (aN.z + bh.z));
                o.z = (1.f - z) * n + z * hp.z;
            }
            {
                const float r = 1.f / (1.f + expf(-(xr.w + aR.w)));
                const float z = 1.f / (1.f + expf(-(xz.w + aZ.w)));
                const float n = tanhf(xn.w + r * (aN.w + bh.w));
                o.w = (1.f - z) * n + z * hp.w;
            }
            *(float4*)(y + (size_t)t * BB * HH + (size_t)pb * HH + pj) = o;

            if (t < TT - 1) {
                const float mk = mask[(size_t)(t + 1) * BB + pb];
                float4 hm = make_float4(o.x * mk, o.y * mk, o.z * mk, o.w * mk);
                *(float4*)(g_hf + (size_t)pb * HH + pj) = hm;
                uint4 uh, ul;
                tf_split(hm.x, uh.x, ul.x);
                tf_split(hm.y, uh.y, ul.y);
                tf_split(hm.z, uh.z, ul.z);
                tf_split(hm.w, uh.w, ul.w);
                *(uint4*)(g_hh + (size_t)pb * HH + pj) = uh;
                *(uint4*)(g_hl + (size_t)pb * HH + pj) = ul;
            }
        }

        // barrier B (skip after final step)
        if (t < TT - 1) {
            tgt += 128;
            __syncthreads();
            if (tid == 0) {
                __threadfence();
                atomicAdd(&g_bars[(bid & 7) * 32], 1u);
                unsigned s;
                do {
                    s = 0;
                    #pragma unroll
                    for (int i = 0; i < 8; i++)
                        s += *((volatile unsigned*)&g_bars[i * 32]);
                } while (s < tgt);
                __threadfence();
            }
            __syncthreads();
        }
    }
}

// ---------------------------------------------------------------------------
// value[m] = sum_j critic[m,j] * W2[j] + b2 ; one block per row m
// ---------------------------------------------------------------------------
__global__ __launch_bounds__(256)
void value_kernel(const float* __restrict__ critic, const float* __restrict__ W2,
                  const float* __restrict__ b2, float* __restrict__ out)
{
    const int m   = blockIdx.x;
    const int tid = threadIdx.x;
    float s = 0.f;
    const float* row = critic + (size_t)m * HH;
    for (int j = tid * 4; j < HH; j += 256 * 4) {
        float4 c4 = *(const float4*)(row + j);
        float4 w4 = *(const float4*)(W2 + j);
        s += c4.x * w4.x + c4.y * w4.y + c4.z * w4.z + c4.w * w4.w;
    }
    #pragma unroll
    for (int off = 16; off > 0; off >>= 1)
        s += __shfl_down_sync(0xffffffffu, s, off);
    __shared__ float red[8];
    if ((tid & 31) == 0) red[tid >> 5] = s;
    __syncthreads();
    if (tid == 0) {
        float t = 0.f;
        #pragma unroll
        for (int w = 0; w < 8; w++) t += red[w];
        out[m] = t + b2[0];
    }
}

__global__ void copy_hout(const float* __restrict__ src, float* __restrict__ dst)
{
    const int i = (blockIdx.x * blockDim.x + threadIdx.x) * 4;
    *(float4*)&dst[i] = *(const float4*)&src[i];
}

// ---------------------------------------------------------------------------
// Launch
// ---------------------------------------------------------------------------
extern "C" void kernel_launch(void* const* d_in, const int* in_sizes, int n_in,
                              void* d_out, int out_size)
{
    const float* hidden = (const float*)d_in[0];
    const float* ws     = (const float*)d_in[1];
    const void*  dones  = (const void*)d_in[2];
    const float* W_emb  = (const float*)d_in[3];
    const float* b_emb  = (const float*)d_in[4];
    const float* Wi     = (const float*)d_in[5];
    const float* bi     = (const float*)d_in[6];
    const float* Wh     = (const float*)d_in[7];
    const float* bhn    = (const float*)d_in[8];
    const float* W1     = (const float*)d_in[9];
    const float* b1     = (const float*)d_in[10];
    const float* W2     = (const float*)d_in[11];
    const float* b2     = (const float*)d_in[12];
    float* out = (float*)d_out;

    float *emb, *xi, *y, *critic, *mask;
    unsigned *whh, *whl, *wembh, *wembl, *wih, *wil, *w1h, *w1l;
    unsigned* barsp;
    int* xiflagp;
    cudaGetSymbolAddress((void**)&emb,    g_emb);
    cudaGetSymbolAddress((void**)&xi,     g_xi);
    cudaGetSymbolAddress((void**)&y,      g_y);
    cudaGetSymbolAddress((void**)&critic, g_critic);
    cudaGetSymbolAddress((void**)&mask,   g_mask);
    cudaGetSymbolAddress((void**)&whh,    g_whh);
    cudaGetSymbolAddress((void**)&whl,    g_whl);
    cudaGetSymbolAddress((void**)&wembh,  g_wembh);
    cudaGetSymbolAddress((void**)&wembl,  g_wembl);
    cudaGetSymbolAddress((void**)&wih,    g_wih);
    cudaGetSymbolAddress((void**)&wil,    g_wil);
    cudaGetSymbolAddress((void**)&w1h,    g_w1h);
    cudaGetSymbolAddress((void**)&w1l,    g_w1l);
    cudaGetSymbolAddress((void**)&barsp,  g_bars);
    cudaGetSymbolAddress((void**)&xiflagp, g_xiflag);

    // fork stream + events (created per call; only correctness + capture call this)
    cudaStream_t s2;
    cudaEvent_t ev1, ev2;
    cudaStreamCreateWithFlags(&s2, cudaStreamNonBlocking);
    cudaEventCreateWithFlags(&ev1, cudaEventDisableTiming);
    cudaEventCreateWithFlags(&ev2, cudaEventDisableTiming);

    // 0) barrier/flag reset; mask; weight/state prep
    cudaMemsetAsync(barsp, 0, 8 * 32 * sizeof(unsigned));
    cudaMemsetAsync(xiflagp, 0, NCHUNK * sizeof(int));
    detect_mask_mode<<<1, 256>>>((const unsigned int*)dones);
    expand_mask<<<MM / 256, 256>>>(dones, mask);
    split_mat<<<(int)(((size_t)HH * H3) / 256), 256>>>(Wh, whh, whl, HH * H3);
    split_mat<<<(int)(((size_t)OBS * HH) / 256), 256>>>(W_emb, wembh, wembl, OBS * HH);
    split_mat<<<(int)(((size_t)HH * H3) / 256), 256>>>(Wi, wih, wil, HH * H3);
    split_mat<<<(int)(((size_t)HH * HH) / 256), 256>>>(W1, w1h, w1l, HH * HH);
    init_h<<<(BB * HH) / 256, 256>>>(hidden, mask);

    // 1) emb = relu(WS @ W_emb + b_emb)
    {
        dim3 grid(HH / 128, MM / 128);
        mma_gemm<1><<<grid, 256>>>(ws, wembh, wembl, b_emb, emb, MM, HH, OBS);
    }

    // fork: xi chunks (+ flags) on s2, concurrent with the scan on main
    cudaEventRecord(ev1, 0);
    cudaStreamWaitEvent(s2, ev1, 0);
    {
        const int MCH = MM / NCHUNK;   // 2048 rows per chunk (16 timesteps)
        dim3 grid(H3 / 128, MCH / 128);
        for (int ch = 0; ch < NCHUNK; ch++) {
            mma_gemm<0><<<grid, 256, 0, s2>>>(emb + (size_t)ch * MCH * HH,
                                              wih, wil, bi,
                                              xi + (size_t)ch * MCH * H3,
                                              MCH, H3, HH);
            set_flag<<<1, 1, 0, s2>>>(ch);
        }
    }
    cudaEventRecord(ev2, s2);

    // 3) GRU scan on main (polls xi flags)
    {
        dim3 grid(COLG, KQ);   // 128 blocks
        gru_scan_mma<<<grid, 256>>>(mask, xi, bhn, y);
    }

    // join s2 before the tail
    cudaStreamWaitEvent(0, ev2, 0);

    // 4) critic = relu(y @ W1 + b1)
    {
        dim3 grid(HH / 128, MM / 128);
        mma_gemm<1><<<grid, 256>>>(y, w1h, w1l, b1, critic, MM, HH, HH);
    }
    // 5) value -> out[131072 ..)
    value_kernel<<<MM, 256>>>(critic, W2, b2, out + (size_t)BB * HH);
    // 6) h_out = y[T-1] -> out[0 .. 131072)
    copy_hout<<<(BB * HH / 4) / 256, 256>>>(y + (size_t)(TT - 1) * BB * HH, out);
}

// round 16
// speedup vs baseline: 1.2308x; 1.2308x over previous
#include <cuda_runtime.h>
#include <cuda_bf16.h>
#include <math.h>

// ---------------------------------------------------------------------------
// CriticRNN: T=128, B=128, OBS=512, H=1024
// GEMMs + GRU scan via tf32 mma.sync (3xtf32 split), double-buffered staging,
// pre-split constant weights; GEMMs 2 blocks/SM; scan = R11/R14-best.
// Critic GEMM fused with the value head (no critic buffer); h_out fused
// into the scan's final step.
// ---------------------------------------------------------------------------

#define TT  128
#define BB  128
#define OBS 512
#define HH  1024
#define H3  3072
#define MM  (TT * BB)   // 16384
#define COLG 32         // h-column groups (32 cols each)
#define KQ   4          // K split factor in the scan
#define KS   (HH / KQ)  // 256 k per split

// Static device scratch (no allocations allowed)
__device__ float    g_emb[(size_t)MM * HH];      // 64 MB
__device__ float    g_xi[(size_t)MM * H3];       // 192 MB
__device__ float    g_y[(size_t)MM * HH];        // 64 MB
__device__ unsigned g_whh[(size_t)HH * H3];      // 12.6 MB  Wh hi (tf32)
__device__ unsigned g_whl[(size_t)HH * H3];      // 12.6 MB  Wh lo (tf32)
__device__ unsigned g_wembh[(size_t)OBS * HH];   // 2.1 MB   W_emb hi
__device__ unsigned g_wembl[(size_t)OBS * HH];   // 2.1 MB   W_emb lo
__device__ unsigned g_wih[(size_t)HH * H3];      // 12.6 MB  Wi hi
__device__ unsigned g_wil[(size_t)HH * H3];      // 12.6 MB  Wi lo
__device__ unsigned g_w1h[(size_t)HH * HH];      // 4.2 MB   W1 hi
__device__ unsigned g_w1l[(size_t)HH * HH];      // 4.2 MB   W1 lo
__device__ unsigned g_hh[BB * HH];               // masked h hi
__device__ unsigned g_hl[BB * HH];               // masked h lo
__device__ float    g_hf[BB * HH];               // masked h fp32
__device__ float    g_part[(size_t)KQ * COLG * BB * 96];  // 6.3 MB partials
__device__ float    g_vpart[(size_t)MM * 8];     // 512 KB value partials
__device__ float    g_mask[MM];
__device__ int      g_bytemode;
__device__ unsigned g_bars[8 * 32];              // striped barrier counters

// ---------------------------------------------------------------------------
// dones layout detection + mask expansion (byte-bool vs int32).
// ---------------------------------------------------------------------------
__global__ void detect_mask_mode(const unsigned int* __restrict__ d)
{
    __shared__ int flag;
    if (threadIdx.x == 0) flag = 0;
    __syncthreads();
    int f = 0;
    for (int i = threadIdx.x; i < MM / 4; i += blockDim.x)
        if (d[i] > 1u) f = 1;
    if (f) atomicOr(&flag, 1);
    __syncthreads();
    if (threadIdx.x == 0) g_bytemode = flag;
}

__global__ void expand_mask(const void* __restrict__ dones, float* __restrict__ mask)
{
    const int i = blockIdx.x * blockDim.x + threadIdx.x;
    if (i >= MM) return;
    int done;
    if (g_bytemode)
        done = ((const unsigned char*)dones)[i] != 0;
    else
        done = ((const int*)dones)[i] != 0;
    mask[i] = done ? 0.f : 1.f;
}

// ---------------------------------------------------------------------------
// tf32 helpers
// ---------------------------------------------------------------------------
__device__ __forceinline__ unsigned f2tf(float x)
{
    unsigned u;
    asm("cvt.rna.tf32.f32 %0, %1;" : "=r"(u) : "f"(x));
    return u;
}
__device__ __forceinline__ void tf_split(float x, unsigned& hi, unsigned& lo)
{
    hi = f2tf(x);
    lo = f2tf(x - __uint_as_float(hi));
}
__device__ __forceinline__ void mma_tf32(float* d,
                                         unsigned a0, unsigned a1, unsigned a2, unsigned a3,
                                         unsigned b0, unsigned b1)
{
    asm("mma.sync.aligned.m16n8k8.row.col.f32.tf32.tf32.f32 "
        "{%0,%1,%2,%3}, {%4,%5,%6,%7}, {%8,%9}, {%0,%1,%2,%3};"
        : "+f"(d[0]), "+f"(d[1]), "+f"(d[2]), "+f"(d[3])
        : "r"(a0), "r"(a1), "r"(a2), "r"(a3), "r"(b0), "r"(b1));
}

// ---------------------------------------------------------------------------
// Prep kernels
// ---------------------------------------------------------------------------
__global__ void split_mat(const float* __restrict__ src,
                          unsigned* __restrict__ hi_out,
                          unsigned* __restrict__ lo_out, int n)
{
    const int i = blockIdx.x * blockDim.x + threadIdx.x;
    if (i >= n) return;
    unsigned hi, lo;
    tf_split(src[i], hi, lo);
    hi_out[i] = hi;
    lo_out[i] = lo;
}

__global__ void init_h(const float* __restrict__ hidden, const float* __restrict__ mask)
{
    const int i = blockIdx.x * blockDim.x + threadIdx.x;
    if (i >= BB * HH) return;
    const float v = hidden[i] * mask[i / HH];
    g_hf[i] = v;
    unsigned hi, lo;
    tf_split(v, hi, lo);
    g_hh[i] = hi;
    g_hl[i] = lo;
}

// ---------------------------------------------------------------------------
// tf32 3x-split tensor-core GEMM, double-buffered, pre-split B:
//   C = op(A@B + bias),  B given as tf32 hi/lo planes. 2 blocks/SM.
// ---------------------------------------------------------------------------
#define PAD 136

template <int DO_RELU>
__global__ __launch_bounds__(256, 2)
void mma_gemm(const float* __restrict__ A,
              const unsigned* __restrict__ Bhg, const unsigned* __restrict__ Blg,
              const float* __restrict__ bias, float* __restrict__ C,
              int M, int N, int K)
{
    __shared__ unsigned Ah[2][8][PAD];
    __shared__ unsigned Al[2][8][PAD];
    __shared__ unsigned Bh[2][8][PAD];
    __shared__ unsigned Bl[2][8][PAD];

    const int tid  = threadIdx.x;
    const int wid  = tid >> 5;
    const int lane = tid & 31;
    const int gid  = lane >> 2;
    const int tig  = lane & 3;

    const int cRow = blockIdx.y * 128;
    const int cCol = blockIdx.x * 128;

    const int warp_m = (wid >> 2) * 64;
    const int warp_n = (wid & 3) * 32;

    const int arow = tid >> 1;
    const int acol = (tid & 1) * 4;
    const float* Ap = A + (size_t)(cRow + arow) * K + acol;

    const int bkrow = tid >> 5;
    const int bcol  = (tid & 31) * 4;
    const unsigned* Bph = Bhg + (size_t)bkrow * N + cCol + bcol;
    const unsigned* Bpl = Blg + (size_t)bkrow * N + cCol + bcol;

    float acc[4][4][4];
    #pragma unroll
    for (int i = 0; i < 4; i++)
        #pragma unroll
        for (int j = 0; j < 4; j++)
            #pragma unroll
            for (int r = 0; r < 4; r++) acc[i][j][r] = 0.f;

    float4 a4 = *(const float4*)(Ap);
    uint4 bh4 = *(const uint4*)(Bph);
    uint4 bl4 = *(const uint4*)(Bpl);
    {
        float av[4] = {a4.x, a4.y, a4.z, a4.w};
        #pragma unroll
        for (int c = 0; c < 4; c++) {
            unsigned hi, lo;
            tf_split(av[c], hi, lo);
            Ah[0][acol + c][arow] = hi;
            Al[0][acol + c][arow] = lo;
        }
        *(uint4*)&Bh[0][bkrow][bcol] = bh4;
        *(uint4*)&Bl[0][bkrow][bcol] = bl4;
    }
    __syncthreads();

    int buf = 0;
    for (int kb = 0; kb < K; kb += 8) {
        const bool more = (kb + 8) < K;
        if (more) {
            a4  = *(const float4*)(Ap + kb + 8);
            bh4 = *(const uint4*)(Bph + (size_t)(kb + 8) * N);
            bl4 = *(const uint4*)(Bpl + (size_t)(kb + 8) * N);
        }

        {
            unsigned bh[4][2], bl[4][2];
            #pragma unroll
            for (int j = 0; j < 4; j++) {
                const int n0 = warp_n + j * 8 + gid;
                bh[j][0] = Bh[buf][tig][n0];
                bh[j][1] = Bh[buf][tig + 4][n0];
                bl[j][0] = Bl[buf][tig][n0];
                bl[j][1] = Bl[buf][tig + 4][n0];
            }
            #pragma unroll
            for (int i = 0; i < 4; i++) {
                const int r0 = warp_m + i * 16 + gid;
                const unsigned ah0 = Ah[buf][tig][r0];
                const unsigned ah1 = Ah[buf][tig][r0 + 8];
                const unsigned ah2 = Ah[buf][tig + 4][r0];
                const unsigned ah3 = Ah[buf][tig + 4][r0 + 8];
                const unsigned al0 = Al[buf][tig][r0];
                const unsigned al1 = Al[buf][tig][r0 + 8];
                const unsigned al2 = Al[buf][tig + 4][r0];
                const unsigned al3 = Al[buf][tig + 4][r0 + 8];
                #pragma unroll
                for (int j = 0; j < 4; j++) {
                    mma_tf32(acc[i][j], ah0, ah1, ah2, ah3, bh[j][0], bh[j][1]);
                    mma_tf32(acc[i][j], ah0, ah1, ah2, ah3, bl[j][0], bl[j][1]);
                    mma_tf32(acc[i][j], al0, al1, al2, al3, bh[j][0], bh[j][1]);
                }
            }
        }

        if (more) {
            const int nb = buf ^ 1;
            float av[4] = {a4.x, a4.y, a4.z, a4.w};
            #pragma unroll
            for (int c = 0; c < 4; c++) {
                unsigned hi, lo;
                tf_split(av[c], hi, lo);
                Ah[nb][acol + c][arow] = hi;
                Al[nb][acol + c][arow] = lo;
            }
            *(uint4*)&Bh[nb][bkrow][bcol] = bh4;
            *(uint4*)&Bl[nb][bkrow][bcol] = bl4;
        }
        __syncthreads();
        buf ^= 1;
    }

    #pragma unroll
    for (int i = 0; i < 4; i++) {
        const int row0 = cRow + warp_m + i * 16 + gid;
        #pragma unroll
        for (int j = 0; j < 4; j++) {
            const int col = cCol + warp_n + j * 8 + tig * 2;
            float2 v0, v1;
            v0.x = acc[i][j][0] + bias[col];
            v0.y = acc[i][j][1] + bias[col + 1];
            v1.x = acc[i][j][2] + bias[col];
            v1.y = acc[i][j][3] + bias[col + 1];
            if (DO_RELU) {
                v0.x = fmaxf(v0.x, 0.f); v0.y = fmaxf(v0.y, 0.f);
                v1.x = fmaxf(v1.x, 0.f); v1.y = fmaxf(v1.y, 0.f);
            }
            *(float2*)&C[(size_t)row0 * N + col]       = v0;
            *(float2*)&C[(size_t)(row0 + 8) * N + col] = v1;
        }
    }
}

// ---------------------------------------------------------------------------
// Critic GEMM fused with value head: computes relu(y@W1+b1) tile and reduces
// against W2 in the epilogue (no critic buffer). Writes deterministic
// per-block row partials g_vpart[row*8 + blockIdx.x].
// ---------------------------------------------------------------------------
__global__ __launch_bounds__(256, 2)
void mma_gemm_value(const float* __restrict__ A,
                    const unsigned* __restrict__ Bhg, const unsigned* __restrict__ Blg,
                    const float* __restrict__ bias, const float* __restrict__ W2,
                    int M, int N, int K)
{
    __shared__ unsigned Ah[2][8][PAD];
    __shared__ unsigned Al[2][8][PAD];
    __shared__ unsigned Bh[2][8][PAD];
    __shared__ unsigned Bl[2][8][PAD];
    __shared__ float vred[128][4];

    const int tid  = threadIdx.x;
    const int wid  = tid >> 5;
    const int lane = tid & 31;
    const int gid  = lane >> 2;
    const int tig  = lane & 3;

    const int cRow = blockIdx.y * 128;
    const int cCol = blockIdx.x * 128;

    const int warp_m = (wid >> 2) * 64;
    const int warp_n = (wid & 3) * 32;

    const int arow = tid >> 1;
    const int acol = (tid & 1) * 4;
    const float* Ap = A + (size_t)(cRow + arow) * K + acol;

    const int bkrow = tid >> 5;
    const int bcol  = (tid & 31) * 4;
    const unsigned* Bph = Bhg + (size_t)bkrow * N + cCol + bcol;
    const unsigned* Bpl = Blg + (size_t)bkrow * N + cCol + bcol;

    float acc[4][4][4];
    #pragma unroll
    for (int i = 0; i < 4; i++)
        #pragma unroll
        for (int j = 0; j < 4; j++)
            #pragma unroll
            for (int r = 0; r < 4; r++) acc[i][j][r] = 0.f;

    float4 a4 = *(const float4*)(Ap);
    uint4 bh4 = *(const uint4*)(Bph);
    uint4 bl4 = *(const uint4*)(Bpl);
    {
        float av[4] = {a4.x, a4.y, a4.z, a4.w};
        #pragma unroll
        for (int c = 0; c < 4; c++) {
            unsigned hi, lo;
            tf_split(av[c], hi, lo);
            Ah[0][acol + c][arow] = hi;
            Al[0][acol + c][arow] = lo;
        }
        *(uint4*)&Bh[0][bkrow][bcol] = bh4;
        *(uint4*)&Bl[0][bkrow][bcol] = bl4;
    }
    __syncthreads();

    int buf = 0;
    for (int kb = 0; kb < K; kb += 8) {
        const bool more = (kb + 8) < K;
        if (more) {
            a4  = *(const float4*)(Ap + kb + 8);
            bh4 = *(const uint4*)(Bph + (size_t)(kb + 8) * N);
            bl4 = *(const uint4*)(Bpl + (size_t)(kb + 8) * N);
        }

        {
            unsigned bh[4][2], bl[4][2];
            #pragma unroll
            for (int j = 0; j < 4; j++) {
                const int n0 = warp_n + j * 8 + gid;
                bh[j][0] = Bh[buf][tig][n0];
                bh[j][1] = Bh[buf][tig + 4][n0];
                bl[j][0] = Bl[buf][tig][n0];
                bl[j][1] = Bl[buf][tig + 4][n0];
            }
            #pragma unroll
            for (int i = 0; i < 4; i++) {
                const int r0 = warp_m + i * 16 + gid;
                const unsigned ah0 = Ah[buf][tig][r0];
                const unsigned ah1 = Ah[buf][tig][r0 + 8];
                const unsigned ah2 = Ah[buf][tig + 4][r0];
                const unsigned ah3 = Ah[buf][tig + 4][r0 + 8];
                const unsigned al0 = Al[buf][tig][r0];
                const unsigned al1 = Al[buf][tig][r0 + 8];
                const unsigned al2 = Al[buf][tig + 4][r0];
                const unsigned al3 = Al[buf][tig + 4][r0 + 8];
                #pragma unroll
                for (int j = 0; j < 4; j++) {
                    mma_tf32(acc[i][j], ah0, ah1, ah2, ah3, bh[j][0], bh[j][1]);
                    mma_tf32(acc[i][j], ah0, ah1, ah2, ah3, bl[j][0], bl[j][1]);
                    mma_tf32(acc[i][j], al0, al1, al2, al3, bh[j][0], bh[j][1]);
                }
            }
        }

        if (more) {
            const int nb = buf ^ 1;
            float av[4] = {a4.x, a4.y, a4.z, a4.w};
            #pragma unroll
            for (int c = 0; c < 4; c++) {
                unsigned hi, lo;
                tf_split(av[c], hi, lo);
                Ah[nb][acol + c][arow] = hi;
                Al[nb][acol + c][arow] = lo;
            }
            *(uint4*)&Bh[nb][bkrow][bcol] = bh4;
            *(uint4*)&Bl[nb][bkrow][bcol] = bl4;
        }
        __syncthreads();
        buf ^= 1;
    }

    // fused epilogue: relu(acc + bias) dot W2, reduced per row
    float rsum[4][2];
    #pragma unroll
    for (int i = 0; i < 4; i++) { rsum[i][0] = 0.f; rsum[i][1] = 0.f; }

    #pragma unroll
    for (int i = 0; i < 4; i++) {
        #pragma unroll
        for (int j = 0; j < 4; j++) {
            const int col = cCol + warp_n + j * 8 + tig * 2;
            const float b0 = bias[col], b1 = bias[col + 1];
            const float w0 = W2[col],  w1 = W2[col + 1];
            rsum[i][0] += fmaxf(acc[i][j][0] + b0, 0.f) * w0
                        + fmaxf(acc[i][j][1] + b1, 0.f) * w1;
            rsum[i][1] += fmaxf(acc[i][j][2] + b0, 0.f) * w0
                        + fmaxf(acc[i][j][3] + b1, 0.f) * w1;
        }
    }
    // reduce over tig (4 lanes, same rows, different cols)
    #pragma unroll
    for (int i = 0; i < 4; i++) {
        #pragma unroll
        for (int r = 0; r < 2; r++) {
            rsum[i][r] += __shfl_xor_sync(0xffffffffu, rsum[i][r], 1);
            rsum[i][r] += __shfl_xor_sync(0xffffffffu, rsum[i][r], 2);
        }
    }
    // cross-warp reduce via smem (4 warps share each row range)
    if (tig == 0) {
        #pragma unroll
        for (int i = 0; i < 4; i++) {
            vred[warp_m + i * 16 + gid][wid & 3]     = rsum[i][0];
            vred[warp_m + i * 16 + gid + 8][wid & 3] = rsum[i][1];
        }
    }
    __syncthreads();
    if (tid < 128) {
        const float s = vred[tid][0] + vred[tid][1] + vred[tid][2] + vred[tid][3];
        g_vpart[(size_t)(cRow + tid) * 8 + blockIdx.x] = s;
    }
}

__global__ void value_finish(const float* __restrict__ b2, float* __restrict__ out)
{
    const int m = blockIdx.x * blockDim.x + threadIdx.x;
    if (m >= MM) return;
    const float* p = g_vpart + (size_t)m * 8;
    float s = 0.f;
    #pragma unroll
    for (int i = 0; i < 8; i++) s += p[i];
    out[m] = s + b2[0];
}

// ---------------------------------------------------------------------------
// Persistent tensor-core GRU scan (R11/R14-best): 256 threads, BK=8
// double-buffered, KQ=4 K-split, striped grid barriers. Writes h_out to
// `hout` on the final step (fused copy_hout).
// ---------------------------------------------------------------------------
__global__ __launch_bounds__(256, 1)
void gru_scan_mma(const float* __restrict__ mask,
                  const float* __restrict__ xi,
                  const float* __restrict__ bhn,
                  float* __restrict__ y,
                  float* __restrict__ hout)
{
    __shared__ unsigned Ah[2][8][136];
    __shared__ unsigned Al[2][8][136];
    __shared__ unsigned Bh[2][8][104];
    __shared__ unsigned Bl[2][8][104];

    const int tid  = threadIdx.x;
    const int wid  = tid >> 5;
    const int lane = tid & 31;
    const int gid  = lane >> 2;
    const int tig  = lane & 3;

    const int c = blockIdx.x;        // colgroup 0..31
    const int q = blockIdx.y;        // k-quarter 0..3
    const int bn32  = c * 32;
    const int kbase = q * KS;
    const int bid   = q * COLG + c;

    const int warp_m = (wid >> 2) * 64;   // 0 / 64
    const int warp_n = (wid & 3) * 24;    // 0,24,48,72

    const int arow = tid >> 1;
    const int acol = (tid & 1) * 4;
    const unsigned* hhp = g_hh + (size_t)arow * HH + kbase + acol;
    const unsigned* hlp = g_hl + (size_t)arow * HH + kbase + acol;

    const bool bv = (tid < 192);
    const int kr = tid / 24, c4 = tid % 24;
    const int bn0 = (c4 >> 3) * 32 + (c4 & 7) * 4;
    const size_t boff = (size_t)(kbase + kr) * H3 + (c4 >> 3) * HH + bn32 + (c4 & 7) * 4;

    float* partp = g_part + (size_t)(q * COLG + c) * BB * 96;

    const int rloc = tid >> 3;
    const int jj   = (tid & 7) * 4;
    const int pb   = q * 32 + rloc;
    const int pj   = bn32 + jj;

    unsigned tgt = 0;

    for (int t = 0; t < TT; t++) {
        // ================= phase 1: mma partials =================
        float acc[4][3][4];
        #pragma unroll
        for (int i = 0; i < 4; i++)
            #pragma unroll
            for (int j = 0; j < 3; j++)
                #pragma unroll
                for (int r = 0; r < 4; r++) acc[i][j][r] = 0.f;

        uint4 pah = *(const uint4*)(hhp);
        uint4 pal = *(const uint4*)(hlp);
        uint4 pbh = bv ? *(const uint4*)(g_whh + boff) : make_uint4(0, 0, 0, 0);
        uint4 pbl = bv ? *(const uint4*)(g_whl + boff) : make_uint4(0, 0, 0, 0);

        {
            Ah[0][acol + 0][arow] = pah.x;
            Ah[0][acol + 1][arow] = pah.y;
            Ah[0][acol + 2][arow] = pah.z;
            Ah[0][acol + 3][arow] = pah.w;
            Al[0][acol + 0][arow] = pal.x;
            Al[0][acol + 1][arow] = pal.y;
            Al[0][acol + 2][arow] = pal.z;
            Al[0][acol + 3][arow] = pal.w;
            if (bv) {
                *(uint4*)&Bh[0][kr][bn0] = pbh;
                *(uint4*)&Bl[0][kr][bn0] = pbl;
            }
        }
        __syncthreads();

        int buf = 0;
        #pragma unroll 1
        for (int kb = 0; kb < KS; kb += 8) {
            const bool more = (kb + 8) < KS;
            if (more) {
                pah = *(const uint4*)(hhp + kb + 8);
                pal = *(const uint4*)(hlp + kb + 8);
                if (bv) {
                    pbh = *(const uint4*)(g_whh + boff + (size_t)(kb + 8) * H3);
                    pbl = *(const uint4*)(g_whl + boff + (size_t)(kb + 8) * H3);
                }
            }

            {
                unsigned bh[3][2], bl[3][2];
                #pragma unroll
                for (int j = 0; j < 3; j++) {
                    const int n0 = warp_n + j * 8 + gid;
                    bh[j][0] = Bh[buf][tig][n0];
                    bh[j][1] = Bh[buf][tig + 4][n0];
                    bl[j][0] = Bl[buf][tig][n0];
                    bl[j][1] = Bl[buf][tig + 4][n0];
                }
                #pragma unroll
                for (int i = 0; i < 4; i++) {
                    const int r0 = warp_m + i * 16 + gid;
                    const unsigned ah0 = Ah[buf][tig][r0];
                    const unsigned ah1 = Ah[buf][tig][r0 + 8];
                    const unsigned ah2 = Ah[buf][tig + 4][r0];
                    const unsigned ah3 = Ah[buf][tig + 4][r0 + 8];
                    const unsigned al0 = Al[buf][tig][r0];
                    const unsigned al1 = Al[buf][tig][r0 + 8];
                    const unsigned al2 = Al[buf][tig + 4][r0];
                    const unsigned al3 = Al[buf][tig + 4][r0 + 8];
                    #pragma unroll
                    for (int j = 0; j < 3; j++) {
                        mma_tf32(acc[i][j], ah0, ah1, ah2, ah3, bh[j][0], bh[j][1]);
                        mma_tf32(acc[i][j], ah0, ah1, ah2, ah3, bl[j][0], bl[j][1]);
                        mma_tf32(acc[i][j], al0, al1, al2, al3, bh[j][0], bh[j][1]);
                    }
                }
            }

            if (more) {
                const int nb = buf ^ 1;
                Ah[nb][acol + 0][arow] = pah.x;
                Ah[nb][acol + 1][arow] = pah.y;
                Ah[nb][acol + 2][arow] = pah.z;
                Ah[nb][acol + 3][arow] = pah.w;
                Al[nb][acol + 0][arow] = pal.x;
                Al[nb][acol + 1][arow] = pal.y;
                Al[nb][acol + 2][arow] = pal.z;
                Al[nb][acol + 3][arow] = pal.w;
                if (bv) {
                    *(uint4*)&Bh[nb][kr][bn0] = pbh;
                    *(uint4*)&Bl[nb][kr][bn0] = pbl;
                }
            }
            __syncthreads();
            buf ^= 1;
        }

        // write partials [128 x 96]
        #pragma unroll
        for (int i = 0; i < 4; i++) {
            const int row = warp_m + i * 16 + gid;
            #pragma unroll
            for (int j = 0; j < 3; j++) {
                const int col = warp_n + j * 8 + tig * 2;
                *(float2*)&partp[(size_t)row * 96 + col] =
                    make_float2(acc[i][j][0], acc[i][j][1]);
                *(float2*)&partp[(size_t)(row + 8) * 96 + col] =
                    make_float2(acc[i][j][2], acc[i][j][3]);
            }
        }

        // barrier A (striped counters)
        tgt += 128;
        __syncthreads();
        if (tid == 0) {
            __threadfence();
            atomicAdd(&g_bars[(bid & 7) * 32], 1u);
            unsigned s;
            do {
                s = 0;
                #pragma unroll
                for (int i = 0; i < 8; i++)
                    s += *((volatile unsigned*)&g_bars[i * 32]);
            } while (s < tgt);
            __threadfence();
        }
        __syncthreads();

        // ================= phase 2: reduce + gates =================
        {
            float4 aR = make_float4(0.f, 0.f, 0.f, 0.f);
            float4 aZ = make_float4(0.f, 0.f, 0.f, 0.f);
            float4 aN = make_float4(0.f, 0.f, 0.f, 0.f);
            #pragma unroll
            for (int qq = 0; qq < KQ; qq++) {
                const float* pp = g_part + ((size_t)(qq * COLG + c) * BB + pb) * 96;
                float4 r4 = *(const float4*)&pp[jj];
                float4 z4 = *(const float4*)&pp[32 + jj];
                float4 n4 = *(const float4*)&pp[64 + jj];
                aR.x += r4.x; aR.y += r4.y; aR.z += r4.z; aR.w += r4.w;
                aZ.x += z4.x; aZ.y += z4.y; aZ.z += z4.z; aZ.w += z4.w;
                aN.x += n4.x; aN.y += n4.y; aN.z += n4.z; aN.w += n4.w;
            }

            const float* xi_t = xi + (size_t)t * BB * H3 + (size_t)pb * H3;
            float4 xr = *(const float4*)(xi_t + pj);
            float4 xz = *(const float4*)(xi_t + HH + pj);
            float4 xn = *(const float4*)(xi_t + 2 * HH + pj);
            float4 hp = *(const float4*)(g_hf + (size_t)pb * HH + pj);
            float4 bh = *(const float4*)(bhn + pj);

            float4 o;
            {
                const float r = 1.f / (1.f + expf(-(xr.x + aR.x)));
                const float z = 1.f / (1.f + expf(-(xz.x + aZ.x)));
                const float n = tanhf(xn.x + r * (aN.x + bh.x));
                o.x = (1.f - z) * n + z * hp.x;
            }
            {
                const float r = 1.f / (1.f + expf(-(xr.y + aR.y)));
                const float z = 1.f / (1.f + expf(-(xz.y + aZ.y)));
                const float n = tanhf(xn.y + r * (aN.y + bh.y));
                o.y = (1.f - z) * n + z * hp.y;
            }
            {
                const float r = 1.f / (1.f + expf(-(xr.z + aR.z)));
                const float z = 1.f / (1.f + expf(-(xz.z + aZ.z)));
                const float n = tanhf(xn.z + r * (aN.z + bh.z));
                o.z = (1.f - z) * n + z * hp.z;
            }
            {
                const float r = 1.f / (1.f + expf(-(xr.w + aR.w)));
                const float z = 1.f / (1.f + expf(-(xz.w + aZ.w)));
                const float n = tanhf(xn.w + r * (aN.w + bh.w));
                o.w = (1.f - z) * n + z * hp.w;
            }
            *(float4*)(y + (size_t)t * BB * HH + (size_t)pb * HH + pj) = o;

            if (t < TT - 1) {
                const float mk = mask[(size_t)(t + 1) * BB + pb];
                float4 hm = make_float4(o.x * mk, o.y * mk, o.z * mk, o.w * mk);
                *(float4*)(g_hf + (size_t)pb * HH + pj) = hm;
                uint4 uh, ul;
                tf_split(hm.x, uh.x, ul.x);
                tf_split(hm.y, uh.y, ul.y);
                tf_split(hm.z, uh.z, ul.z);
                tf_split(hm.w, uh.w, ul.w);
                *(uint4*)(g_hh + (size_t)pb * HH + pj) = uh;
                *(uint4*)(g_hl + (size_t)pb * HH + pj) = ul;
            } else {
                // fused h_out = y[T-1]
                *(float4*)(hout + (size_t)pb * HH + pj) = o;
            }
        }

        // barrier B (skip after final step)
        if (t < TT - 1) {
            tgt += 128;
            __syncthreads();
            if (tid == 0) {
                __threadfence();
                atomicAdd(&g_bars[(bid & 7) * 32], 1u);
                unsigned s;
                do {
                    s = 0;
                    #pragma unroll
                    for (int i = 0; i < 8; i++)
                        s += *((volatile unsigned*)&g_bars[i * 32]);
                } while (s < tgt);
                __threadfence();
            }
            __syncthreads();
        }
    }
}

// ---------------------------------------------------------------------------
// Launch
// ---------------------------------------------------------------------------
extern "C" void kernel_launch(void* const* d_in, const int* in_sizes, int n_in,
                              void* d_out, int out_size)
{
    const float* hidden = (const float*)d_in[0];
    const float* ws     = (const float*)d_in[1];
    const void*  dones  = (const void*)d_in[2];
    const float* W_emb  = (const float*)d_in[3];
    const float* b_emb  = (const float*)d_in[4];
    const float* Wi     = (const float*)d_in[5];
    const float* bi     = (const float*)d_in[6];
    const float* Wh     = (const float*)d_in[7];
    const float* bhn    = (const float*)d_in[8];
    const float* W1     = (const float*)d_in[9];
    const float* b1     = (const float*)d_in[10];
    const float* W2     = (const float*)d_in[11];
    const float* b2     = (const float*)d_in[12];
    float* out = (float*)d_out;

    float *emb, *xi, *y, *mask;
    unsigned *whh, *whl, *wembh, *wembl, *wih, *wil, *w1h, *w1l;
    unsigned* barsp;
    cudaGetSymbolAddress((void**)&emb,    g_emb);
    cudaGetSymbolAddress((void**)&xi,     g_xi);
    cudaGetSymbolAddress((void**)&y,      g_y);
    cudaGetSymbolAddress((void**)&mask,   g_mask);
    cudaGetSymbolAddress((void**)&whh,    g_whh);
    cudaGetSymbolAddress((void**)&whl,    g_whl);
    cudaGetSymbolAddress((void**)&wembh,  g_wembh);
    cudaGetSymbolAddress((void**)&wembl,  g_wembl);
    cudaGetSymbolAddress((void**)&wih,    g_wih);
    cudaGetSymbolAddress((void**)&wil,    g_wil);
    cudaGetSymbolAddress((void**)&w1h,    g_w1h);
    cudaGetSymbolAddress((void**)&w1l,    g_w1l);
    cudaGetSymbolAddress((void**)&barsp,  g_bars);

    // 0) barrier reset; mask; weight/state prep (all constant splits)
    cudaMemsetAsync(barsp, 0, 8 * 32 * sizeof(unsigned));
    detect_mask_mode<<<1, 256>>>((const unsigned int*)dones);
    expand_mask<<<MM / 256, 256>>>(dones, mask);
    split_mat<<<(int)(((size_t)HH * H3) / 256), 256>>>(Wh, whh, whl, HH * H3);
    split_mat<<<(int)(((size_t)OBS * HH) / 256), 256>>>(W_emb, wembh, wembl, OBS * HH);
    split_mat<<<(int)(((size_t)HH * H3) / 256), 256>>>(Wi, wih, wil, HH * H3);
    split_mat<<<(int)(((size_t)HH * HH) / 256), 256>>>(W1, w1h, w1l, HH * HH);
    init_h<<<(BB * HH) / 256, 256>>>(hidden, mask);

    // 1) emb = relu(WS @ W_emb + b_emb)
    {
        dim3 grid(HH / 128, MM / 128);
        mma_gemm<1><<<grid, 256>>>(ws, wembh, wembl, b_emb, emb, MM, HH, OBS);
    }
    // 2) xi = emb @ Wi + bi
    {
        dim3 grid(H3 / 128, MM / 128);
        mma_gemm<0><<<grid, 256>>>(emb, wih, wil, bi, xi, MM, H3, HH);
    }
    // 3) GRU scan (writes y and h_out)
    {
        dim3 grid(COLG, KQ);   // 128 blocks
        gru_scan_mma<<<grid, 256>>>(mask, xi, bhn, y, out);
    }
    // 4) critic GEMM fused with value head -> g_vpart
    {
        dim3 grid(HH / 128, MM / 128);
        mma_gemm_value<<<grid, 256>>>(y, w1h, w1l, b1, W2, MM, HH, HH);
    }
    // 5) value finish -> out[131072 ..)
    value_finish<<<MM / 256, 256>>>(b2, out + (size_t)BB * HH);
}

// round 17
// speedup vs baseline: 1.3810x; 1.1221x over previous
#include <cuda_runtime.h>
#include <cuda_bf16.h>
#include <math.h>

// ---------------------------------------------------------------------------
// CriticRNN: T=128, B=128, OBS=512, H=1024
// Feed-forward GEMMs: 2-mma tf32 split (A hi+lo, B tf32-rounded) — err ~1e-4.
// GRU scan: full 3-mma split (error-critical recurrence), R11/R14 structure.
// Critic GEMM fused with value head; h_out fused into scan's final step.
// ---------------------------------------------------------------------------

#define TT  128
#define BB  128
#define OBS 512
#define HH  1024
#define H3  3072
#define MM  (TT * BB)   // 16384
#define COLG 32         // h-column groups (32 cols each)
#define KQ   4          // K split factor in the scan
#define KS   (HH / KQ)  // 256 k per split

// Static device scratch (no allocations allowed)
__device__ float    g_emb[(size_t)MM * HH];      // 64 MB
__device__ float    g_xi[(size_t)MM * H3];       // 192 MB
__device__ float    g_y[(size_t)MM * HH];        // 64 MB
__device__ unsigned g_whh[(size_t)HH * H3];      // 12.6 MB  Wh hi (tf32)
__device__ unsigned g_whl[(size_t)HH * H3];      // 12.6 MB  Wh lo (tf32)
__device__ unsigned g_wembh[(size_t)OBS * HH];   // 2.1 MB   W_emb tf32
__device__ unsigned g_wih[(size_t)HH * H3];      // 12.6 MB  Wi tf32
__device__ unsigned g_w1h[(size_t)HH * HH];      // 4.2 MB   W1 tf32
__device__ unsigned g_hh[BB * HH];               // masked h hi
__device__ unsigned g_hl[BB * HH];               // masked h lo
__device__ float    g_hf[BB * HH];               // masked h fp32
__device__ float    g_part[(size_t)KQ * COLG * BB * 96];  // 6.3 MB partials
__device__ float    g_vpart[(size_t)MM * 8];     // 512 KB value partials
__device__ float    g_mask[MM];
__device__ int      g_bytemode;
__device__ unsigned g_bars[8 * 32];              // striped barrier counters

// ---------------------------------------------------------------------------
// dones layout detection + mask expansion (byte-bool vs int32).
// ---------------------------------------------------------------------------
__global__ void detect_mask_mode(const unsigned int* __restrict__ d)
{
    __shared__ int flag;
    if (threadIdx.x == 0) flag = 0;
    __syncthreads();
    int f = 0;
    for (int i = threadIdx.x; i < MM / 4; i += blockDim.x)
        if (d[i] > 1u) f = 1;
    if (f) atomicOr(&flag, 1);
    __syncthreads();
    if (threadIdx.x == 0) g_bytemode = flag;
}

__global__ void expand_mask(const void* __restrict__ dones, float* __restrict__ mask)
{
    const int i = blockIdx.x * blockDim.x + threadIdx.x;
    if (i >= MM) return;
    int done;
    if (g_bytemode)
        done = ((const unsigned char*)dones)[i] != 0;
    else
        done = ((const int*)dones)[i] != 0;
    mask[i] = done ? 0.f : 1.f;
}

// ---------------------------------------------------------------------------
// tf32 helpers
// ---------------------------------------------------------------------------
__device__ __forceinline__ unsigned f2tf(float x)
{
    unsigned u;
    asm("cvt.rna.tf32.f32 %0, %1;" : "=r"(u) : "f"(x));
    return u;
}
__device__ __forceinline__ void tf_split(float x, unsigned& hi, unsigned& lo)
{
    hi = f2tf(x);
    lo = f2tf(x - __uint_as_float(hi));
}
__device__ __forceinline__ void mma_tf32(float* d,
                                         unsigned a0, unsigned a1, unsigned a2, unsigned a3,
                                         unsigned b0, unsigned b1)
{
    asm("mma.sync.aligned.m16n8k8.row.col.f32.tf32.tf32.f32 "
        "{%0,%1,%2,%3}, {%4,%5,%6,%7}, {%8,%9}, {%0,%1,%2,%3};"
        : "+f"(d[0]), "+f"(d[1]), "+f"(d[2]), "+f"(d[3])
        : "r"(a0), "r"(a1), "r"(a2), "r"(a3), "r"(b0), "r"(b1));
}

// ---------------------------------------------------------------------------
// Prep kernels
// ---------------------------------------------------------------------------
__global__ void split_mat(const float* __restrict__ src,
                          unsigned* __restrict__ hi_out,
                          unsigned* __restrict__ lo_out, int n)
{
    const int i = blockIdx.x * blockDim.x + threadIdx.x;
    if (i >= n) return;
    unsigned hi, lo;
    tf_split(src[i], hi, lo);
    hi_out[i] = hi;
    lo_out[i] = lo;
}

__global__ void round_mat(const float* __restrict__ src,
                          unsigned* __restrict__ hi_out, int n)
{
    const int i = blockIdx.x * blockDim.x + threadIdx.x;
    if (i >= n) return;
    hi_out[i] = f2tf(src[i]);
}

__global__ void init_h(const float* __restrict__ hidden, const float* __restrict__ mask)
{
    const int i = blockIdx.x * blockDim.x + threadIdx.x;
    if (i >= BB * HH) return;
    const float v = hidden[i] * mask[i / HH];
    g_hf[i] = v;
    unsigned hi, lo;
    tf_split(v, hi, lo);
    g_hh[i] = hi;
    g_hl[i] = lo;
}

// ---------------------------------------------------------------------------
// 2-mma tf32 GEMM (A hi+lo split, B tf32-rounded), double-buffered:
//   C = op(A@B + bias). Block 128x128, BK=8, 256 thr, 2 blocks/SM.
// ---------------------------------------------------------------------------
#define PAD 136

template <int DO_RELU>
__global__ __launch_bounds__(256, 2)
void mma_gemm(const float* __restrict__ A,
              const unsigned* __restrict__ Bhg,
              const float* __restrict__ bias, float* __restrict__ C,
              int M, int N, int K)
{
    __shared__ unsigned Ah[2][8][PAD];
    __shared__ unsigned Al[2][8][PAD];
    __shared__ unsigned Bh[2][8][PAD];

    const int tid  = threadIdx.x;
    const int wid  = tid >> 5;
    const int lane = tid & 31;
    const int gid  = lane >> 2;
    const int tig  = lane & 3;

    const int cRow = blockIdx.y * 128;
    const int cCol = blockIdx.x * 128;

    const int warp_m = (wid >> 2) * 64;
    const int warp_n = (wid & 3) * 32;

    const int arow = tid >> 1;
    const int acol = (tid & 1) * 4;
    const float* Ap = A + (size_t)(cRow + arow) * K + acol;

    const int bkrow = tid >> 5;
    const int bcol  = (tid & 31) * 4;
    const unsigned* Bph = Bhg + (size_t)bkrow * N + cCol + bcol;

    float acc[4][4][4];
    #pragma unroll
    for (int i = 0; i < 4; i++)
        #pragma unroll
        for (int j = 0; j < 4; j++)
            #pragma unroll
            for (int r = 0; r < 4; r++) acc[i][j][r] = 0.f;

    float4 a4 = *(const float4*)(Ap);
    uint4 bh4 = *(const uint4*)(Bph);
    {
        float av[4] = {a4.x, a4.y, a4.z, a4.w};
        #pragma unroll
        for (int c = 0; c < 4; c++) {
            unsigned hi, lo;
            tf_split(av[c], hi, lo);
            Ah[0][acol + c][arow] = hi;
            Al[0][acol + c][arow] = lo;
        }
        *(uint4*)&Bh[0][bkrow][bcol] = bh4;
    }
    __syncthreads();

    int buf = 0;
    for (int kb = 0; kb < K; kb += 8) {
        const bool more = (kb + 8) < K;
        if (more) {
            a4  = *(const float4*)(Ap + kb + 8);
            bh4 = *(const uint4*)(Bph + (size_t)(kb + 8) * N);
        }

        {
            unsigned bh[4][2];
            #pragma unroll
            for (int j = 0; j < 4; j++) {
                const int n0 = warp_n + j * 8 + gid;
                bh[j][0] = Bh[buf][tig][n0];
                bh[j][1] = Bh[buf][tig + 4][n0];
            }
            #pragma unroll
            for (int i = 0; i < 4; i++) {
                const int r0 = warp_m + i * 16 + gid;
                const unsigned ah0 = Ah[buf][tig][r0];
                const unsigned ah1 = Ah[buf][tig][r0 + 8];
                const unsigned ah2 = Ah[buf][tig + 4][r0];
                const unsigned ah3 = Ah[buf][tig + 4][r0 + 8];
                const unsigned al0 = Al[buf][tig][r0];
                const unsigned al1 = Al[buf][tig][r0 + 8];
                const unsigned al2 = Al[buf][tig + 4][r0];
                const unsigned al3 = Al[buf][tig + 4][r0 + 8];
                #pragma unroll
                for (int j = 0; j < 4; j++) {
                    mma_tf32(acc[i][j], ah0, ah1, ah2, ah3, bh[j][0], bh[j][1]);
                    mma_tf32(acc[i][j], al0, al1, al2, al3, bh[j][0], bh[j][1]);
                }
            }
        }

        if (more) {
            const int nb = buf ^ 1;
            float av[4] = {a4.x, a4.y, a4.z, a4.w};
            #pragma unroll
            for (int c = 0; c < 4; c++) {
                unsigned hi, lo;
                tf_split(av[c], hi, lo);
                Ah[nb][acol + c][arow] = hi;
                Al[nb][acol + c][arow] = lo;
            }
            *(uint4*)&Bh[nb][bkrow][bcol] = bh4;
        }
        __syncthreads();
        buf ^= 1;
    }

    #pragma unroll
    for (int i = 0; i < 4; i++) {
        const int row0 = cRow + warp_m + i * 16 + gid;
        #pragma unroll
        for (int j = 0; j < 4; j++) {
            const int col = cCol + warp_n + j * 8 + tig * 2;
            float2 v0, v1;
            v0.x = acc[i][j][0] + bias[col];
            v0.y = acc[i][j][1] + bias[col + 1];
            v1.x = acc[i][j][2] + bias[col];
            v1.y = acc[i][j][3] + bias[col + 1];
            if (DO_RELU) {
                v0.x = fmaxf(v0.x, 0.f); v0.y = fmaxf(v0.y, 0.f);
                v1.x = fmaxf(v1.x, 0.f); v1.y = fmaxf(v1.y, 0.f);
            }
            *(float2*)&C[(size_t)row0 * N + col]       = v0;
            *(float2*)&C[(size_t)(row0 + 8) * N + col] = v1;
        }
    }
}

// ---------------------------------------------------------------------------
// Critic GEMM (2-mma split) fused with value head: per-block row partials
// g_vpart[row*8 + blockIdx.x] of relu(y@W1+b1) dot W2.
// ---------------------------------------------------------------------------
__global__ __launch_bounds__(256, 2)
void mma_gemm_value(const float* __restrict__ A,
                    const unsigned* __restrict__ Bhg,
                    const float* __restrict__ bias, const float* __restrict__ W2,
                    int M, int N, int K)
{
    __shared__ unsigned Ah[2][8][PAD];
    __shared__ unsigned Al[2][8][PAD];
    __shared__ unsigned Bh[2][8][PAD];
    __shared__ float vred[128][4];

    const int tid  = threadIdx.x;
    const int wid  = tid >> 5;
    const int lane = tid & 31;
    const int gid  = lane >> 2;
    const int tig  = lane & 3;

    const int cRow = blockIdx.y * 128;
    const int cCol = blockIdx.x * 128;

    const int warp_m = (wid >> 2) * 64;
    const int warp_n = (wid & 3) * 32;

    const int arow = tid >> 1;
    const int acol = (tid & 1) * 4;
    const float* Ap = A + (size_t)(cRow + arow) * K + acol;

    const int bkrow = tid >> 5;
    const int bcol  = (tid & 31) * 4;
    const unsigned* Bph = Bhg + (size_t)bkrow * N + cCol + bcol;

    float acc[4][4][4];
    #pragma unroll
    for (int i = 0; i < 4; i++)
        #pragma unroll
        for (int j = 0; j < 4; j++)
            #pragma unroll
            for (int r = 0; r < 4; r++) acc[i][j][r] = 0.f;

    float4 a4 = *(const float4*)(Ap);
    uint4 bh4 = *(const uint4*)(Bph);
    {
        float av[4] = {a4.x, a4.y, a4.z, a4.w};
        #pragma unroll
        for (int c = 0; c < 4; c++) {
            unsigned hi, lo;
            tf_split(av[c], hi, lo);
            Ah[0][acol + c][arow] = hi;
            Al[0][acol + c][arow] = lo;
        }
        *(uint4*)&Bh[0][bkrow][bcol] = bh4;
    }
    __syncthreads();

    int buf = 0;
    for (int kb = 0; kb < K; kb += 8) {
        const bool more = (kb + 8) < K;
        if (more) {
            a4  = *(const float4*)(Ap + kb + 8);
            bh4 = *(const uint4*)(Bph + (size_t)(kb + 8) * N);
        }

        {
            unsigned bh[4][2];
            #pragma unroll
            for (int j = 0; j < 4; j++) {
                const int n0 = warp_n + j * 8 + gid;
                bh[j][0] = Bh[buf][tig][n0];
                bh[j][1] = Bh[buf][tig + 4][n0];
            }
            #pragma unroll
            for (int i = 0; i < 4; i++) {
                const int r0 = warp_m + i * 16 + gid;
                const unsigned ah0 = Ah[buf][tig][r0];
                const unsigned ah1 = Ah[buf][tig][r0 + 8];
                const unsigned ah2 = Ah[buf][tig + 4][r0];
                const unsigned ah3 = Ah[buf][tig + 4][r0 + 8];
                const unsigned al0 = Al[buf][tig][r0];
                const unsigned al1 = Al[buf][tig][r0 + 8];
                const unsigned al2 = Al[buf][tig + 4][r0];
                const unsigned al3 = Al[buf][tig + 4][r0 + 8];
                #pragma unroll
                for (int j = 0; j < 4; j++) {
                    mma_tf32(acc[i][j], ah0, ah1, ah2, ah3, bh[j][0], bh[j][1]);
                    mma_tf32(acc[i][j], al0, al1, al2, al3, bh[j][0], bh[j][1]);
                }
            }
        }

        if (more) {
            const int nb = buf ^ 1;
            float av[4] = {a4.x, a4.y, a4.z, a4.w};
            #pragma unroll
            for (int c = 0; c < 4; c++) {
                unsigned hi, lo;
                tf_split(av[c], hi, lo);
                Ah[nb][acol + c][arow] = hi;
                Al[nb][acol + c][arow] = lo;
            }
            *(uint4*)&Bh[nb][bkrow][bcol] = bh4;
        }
        __syncthreads();
        buf ^= 1;
    }

    // fused epilogue: relu(acc + bias) dot W2, reduced per row
    float rsum[4][2];
    #pragma unroll
    for (int i = 0; i < 4; i++) { rsum[i][0] = 0.f; rsum[i][1] = 0.f; }

    #pragma unroll
    for (int i = 0; i < 4; i++) {
        #pragma unroll
        for (int j = 0; j < 4; j++) {
            const int col = cCol + warp_n + j * 8 + tig * 2;
            const float b0 = bias[col], b1 = bias[col + 1];
            const float w0 = W2[col],  w1 = W2[col + 1];
            rsum[i][0] += fmaxf(acc[i][j][0] + b0, 0.f) * w0
                        + fmaxf(acc[i][j][1] + b1, 0.f) * w1;
            rsum[i][1] += fmaxf(acc[i][j][2] + b0, 0.f) * w0
                        + fmaxf(acc[i][j][3] + b1, 0.f) * w1;
        }
    }
    #pragma unroll
    for (int i = 0; i < 4; i++) {
        #pragma unroll
        for (int r = 0; r < 2; r++) {
            rsum[i][r] += __shfl_xor_sync(0xffffffffu, rsum[i][r], 1);
            rsum[i][r] += __shfl_xor_sync(0xffffffffu, rsum[i][r], 2);
        }
    }
    if (tig == 0) {
        #pragma unroll
        for (int i = 0; i < 4; i++) {
            vred[warp_m + i * 16 + gid][wid & 3]     = rsum[i][0];
            vred[warp_m + i * 16 + gid + 8][wid & 3] = rsum[i][1];
        }
    }
    __syncthreads();
    if (tid < 128) {
        const float s = vred[tid][0] + vred[tid][1] + vred[tid][2] + vred[tid][3];
        g_vpart[(size_t)(cRow + tid) * 8 + blockIdx.x] = s;
    }
}

__global__ void value_finish(const float* __restrict__ b2, float* __restrict__ out)
{
    const int m = blockIdx.x * blockDim.x + threadIdx.x;
    if (m >= MM) return;
    const float* p = g_vpart + (size_t)m * 8;
    float s = 0.f;
    #pragma unroll
    for (int i = 0; i < 8; i++) s += p[i];
    out[m] = s + b2[0];
}

// ---------------------------------------------------------------------------
// Persistent tensor-core GRU scan (3-mma split, R11/R14-best): 256 threads,
// BK=8 double-buffered, KQ=4 K-split, striped grid barriers. h_out fused.
// ---------------------------------------------------------------------------
__global__ __launch_bounds__(256, 1)
void gru_scan_mma(const float* __restrict__ mask,
                  const float* __restrict__ xi,
                  const float* __restrict__ bhn,
                  float* __restrict__ y,
                  float* __restrict__ hout)
{
    __shared__ unsigned Ah[2][8][136];
    __shared__ unsigned Al[2][8][136];
    __shared__ unsigned Bh[2][8][104];
    __shared__ unsigned Bl[2][8][104];

    const int tid  = threadIdx.x;
    const int wid  = tid >> 5;
    const int lane = tid & 31;
    const int gid  = lane >> 2;
    const int tig  = lane & 3;

    const int c = blockIdx.x;
    const int q = blockIdx.y;
    const int bn32  = c * 32;
    const int kbase = q * KS;
    const int bid   = q * COLG + c;

    const int warp_m = (wid >> 2) * 64;
    const int warp_n = (wid & 3) * 24;

    const int arow = tid >> 1;
    const int acol = (tid & 1) * 4;
    const unsigned* hhp = g_hh + (size_t)arow * HH + kbase + acol;
    const unsigned* hlp = g_hl + (size_t)arow * HH + kbase + acol;

    const bool bv = (tid < 192);
    const int kr = tid / 24, c4 = tid % 24;
    const int bn0 = (c4 >> 3) * 32 + (c4 & 7) * 4;
    const size_t boff = (size_t)(kbase + kr) * H3 + (c4 >> 3) * HH + bn32 + (c4 & 7) * 4;

    float* partp = g_part + (size_t)(q * COLG + c) * BB * 96;

    const int rloc = tid >> 3;
    const int jj   = (tid & 7) * 4;
    const int pb   = q * 32 + rloc;
    const int pj   = bn32 + jj;

    unsigned tgt = 0;

    for (int t = 0; t < TT; t++) {
        float acc[4][3][4];
        #pragma unroll
        for (int i = 0; i < 4; i++)
            #pragma unroll
            for (int j = 0; j < 3; j++)
                #pragma unroll
                for (int r = 0; r < 4; r++) acc[i][j][r] = 0.f;

        uint4 pah = *(const uint4*)(hhp);
        uint4 pal = *(const uint4*)(hlp);
        uint4 pbh = bv ? *(const uint4*)(g_whh + boff) : make_uint4(0, 0, 0, 0);
        uint4 pbl = bv ? *(const uint4*)(g_whl + boff) : make_uint4(0, 0, 0, 0);

        {
            Ah[0][acol + 0][arow] = pah.x;
            Ah[0][acol + 1][arow] = pah.y;
            Ah[0][acol + 2][arow] = pah.z;
            Ah[0][acol + 3][arow] = pah.w;
            Al[0][acol + 0][arow] = pal.x;
            Al[0][acol + 1][arow] = pal.y;
            Al[0][acol + 2][arow] = pal.z;
            Al[0][acol + 3][arow] = pal.w;
            if (bv) {
                *(uint4*)&Bh[0][kr][bn0] = pbh;
                *(uint4*)&Bl[0][kr][bn0] = pbl;
            }
        }
        __syncthreads();

        int buf = 0;
        #pragma unroll 1
        for (int kb = 0; kb < KS; kb += 8) {
            const bool more = (kb + 8) < KS;
            if (more) {
                pah = *(const uint4*)(hhp + kb + 8);
                pal = *(const uint4*)(hlp + kb + 8);
                if (bv) {
                    pbh = *(const uint4*)(g_whh + boff + (size_t)(kb + 8) * H3);
                    pbl = *(const uint4*)(g_whl + boff + (size_t)(kb + 8) * H3);
                }
            }

            {
                unsigned bh[3][2], bl[3][2];
                #pragma unroll
                for (int j = 0; j < 3; j++) {
                    const int n0 = warp_n + j * 8 + gid;
                    bh[j][0] = Bh[buf][tig][n0];
                    bh[j][1] = Bh[buf][tig + 4][n0];
                    bl[j][0] = Bl[buf][tig][n0];
                    bl[j][1] = Bl[buf][tig + 4][n0];
                }
                #pragma unroll
                for (int i = 0; i < 4; i++) {
                    const int r0 = warp_m + i * 16 + gid;
                    const unsigned ah0 = Ah[buf][tig][r0];
                    const unsigned ah1 = Ah[buf][tig][r0 + 8];
                    const unsigned ah2 = Ah[buf][tig + 4][r0];
                    const unsigned ah3 = Ah[buf][tig + 4][r0 + 8];
                    const unsigned al0 = Al[buf][tig][r0];
                    const unsigned al1 = Al[buf][tig][r0 + 8];
                    const unsigned al2 = Al[buf][tig + 4][r0];
                    const unsigned al3 = Al[buf][tig + 4][r0 + 8];
                    #pragma unroll
                    for (int j = 0; j < 3; j++) {
                        mma_tf32(acc[i][j], ah0, ah1, ah2, ah3, bh[j][0], bh[j][1]);
                        mma_tf32(acc[i][j], ah0, ah1, ah2, ah3, bl[j][0], bl[j][1]);
                        mma_tf32(acc[i][j], al0, al1, al2, al3, bh[j][0], bh[j][1]);
                    }
                }
            }

            if (more) {
                const int nb = buf ^ 1;
                Ah[nb][acol + 0][arow] = pah.x;
                Ah[nb][acol + 1][arow] = pah.y;
                Ah[nb][acol + 2][arow] = pah.z;
                Ah[nb][acol + 3][arow] = pah.w;
                Al[nb][acol + 0][arow] = pal.x;
                Al[nb][acol + 1][arow] = pal.y;
                Al[nb][acol + 2][arow] = pal.z;
                Al[nb][acol + 3][arow] = pal.w;
                if (bv) {
                    *(uint4*)&Bh[nb][kr][bn0] = pbh;
                    *(uint4*)&Bl[nb][kr][bn0] = pbl;
                }
            }
            __syncthreads();
            buf ^= 1;
        }

        #pragma unroll
        for (int i = 0; i < 4; i++) {
            const int row = warp_m + i * 16 + gid;
            #pragma unroll
            for (int j = 0; j < 3; j++) {
                const int col = warp_n + j * 8 + tig * 2;
                *(float2*)&partp[(size_t)row * 96 + col] =
                    make_float2(acc[i][j][0], acc[i][j][1]);
                *(float2*)&partp[(size_t)(row + 8) * 96 + col] =
                    make_float2(acc[i][j][2], acc[i][j][3]);
            }
        }

        // barrier A
        tgt += 128;
        __syncthreads();
        if (tid == 0) {
            __threadfence();
            atomicAdd(&g_bars[(bid & 7) * 32], 1u);
            unsigned s;
            do {
                s = 0;
                #pragma unroll
                for (int i = 0; i < 8; i++)
                    s += *((volatile unsigned*)&g_bars[i * 32]);
            } while (s < tgt);
            __threadfence();
        }
        __syncthreads();

        // phase 2
        {
            float4 aR = make_float4(0.f, 0.f, 0.f, 0.f);
            float4 aZ = make_float4(0.f, 0.f, 0.f, 0.f);
            float4 aN = make_float4(0.f, 0.f, 0.f, 0.f);
            #pragma unroll
            for (int qq = 0; qq < KQ; qq++) {
                const float* pp = g_part + ((size_t)(qq * COLG + c) * BB + pb) * 96;
                float4 r4 = *(const float4*)&pp[jj];
                float4 z4 = *(const float4*)&pp[32 + jj];
                float4 n4 = *(const float4*)&pp[64 + jj];
                aR.x += r4.x; aR.y += r4.y; aR.z += r4.z; aR.w += r4.w;
                aZ.x += z4.x; aZ.y += z4.y; aZ.z += z4.z; aZ.w += z4.w;
                aN.x += n4.x; aN.y += n4.y; aN.z += n4.z; aN.w += n4.w;
            }

            const float* xi_t = xi + (size_t)t * BB * H3 + (size_t)pb * H3;
            float4 xr = *(const float4*)(xi_t + pj);
            float4 xz = *(const float4*)(xi_t + HH + pj);
            float4 xn = *(const float4*)(xi_t + 2 * HH + pj);
            float4 hp = *(const float4*)(g_hf + (size_t)pb * HH + pj);
            float4 bh = *(const float4*)(bhn + pj);

            float4 o;
            {
                const float r = 1.f / (1.f + expf(-(xr.x + aR.x)));
                const float z = 1.f / (1.f + expf(-(xz.x + aZ.x)));
                const float n = tanhf(xn.x + r * (aN.x + bh.x));
                o.x = (1.f - z) * n + z * hp.x;
            }
            {
                const float r = 1.f / (1.f + expf(-(xr.y + aR.y)));
                const float z = 1.f / (1.f + expf(-(xz.y + aZ.y)));
                const float n = tanhf(xn.y + r * (aN.y + bh.y));
                o.y = (1.f - z) * n + z * hp.y;
            }
            {
                const float r = 1.f / (1.f + expf(-(xr.z + aR.z)));
                const float z = 1.f / (1.f + expf(-(xz.z + aZ.z)));
                const float n = tanhf(xn.z + r * (aN.z + bh.z));
                o.z = (1.f - z) * n + z * hp.z;
            }
            {
                const float r = 1.f / (1.f + expf(-(xr.w + aR.w)));
                const float z = 1.f / (1.f + expf(-(xz.w + aZ.w)));
                const float n = tanhf(xn.w + r * (aN.w + bh.w));
                o.w = (1.f - z) * n + z * hp.w;
            }
            *(float4*)(y + (size_t)t * BB * HH + (size_t)pb * HH + pj) = o;

            if (t < TT - 1) {
                const float mk = mask[(size_t)(t + 1) * BB + pb];
                float4 hm = make_float4(o.x * mk, o.y * mk, o.z * mk, o.w * mk);
                *(float4*)(g_hf + (size_t)pb * HH + pj) = hm;
                uint4 uh, ul;
                tf_split(hm.x, uh.x, ul.x);
                tf_split(hm.y, uh.y, ul.y);
                tf_split(hm.z, uh.z, ul.z);
                tf_split(hm.w, uh.w, ul.w);
                *(uint4*)(g_hh + (size_t)pb * HH + pj) = uh;
                *(uint4*)(g_hl + (size_t)pb * HH + pj) = ul;
            } else {
                *(float4*)(hout + (size_t)pb * HH + pj) = o;
            }
        }

        // barrier B
        if (t < TT - 1) {
            tgt += 128;
            __syncthreads();
            if (tid == 0) {
                __threadfence();
                atomicAdd(&g_bars[(bid & 7) * 32], 1u);
                unsigned s;
                do {
                    s = 0;
                    #pragma unroll
                    for (int i = 0; i < 8; i++)
                        s += *((volatile unsigned*)&g_bars[i * 32]);
                } while (s < tgt);
                __threadfence();
            }
            __syncthreads();
        }
    }
}

// ---------------------------------------------------------------------------
// Launch
// ---------------------------------------------------------------------------
extern "C" void kernel_launch(void* const* d_in, const int* in_sizes, int n_in,
                              void* d_out, int out_size)
{
    const float* hidden = (const float*)d_in[0];
    const float* ws     = (const float*)d_in[1];
    const void*  dones  = (const void*)d_in[2];
    const float* W_emb  = (const float*)d_in[3];
    const float* b_emb  = (const float*)d_in[4];
    const float* Wi     = (const float*)d_in[5];
    const float* bi     = (const float*)d_in[6];
    const float* Wh     = (const float*)d_in[7];
    const float* bhn    = (const float*)d_in[8];
    const float* W1     = (const float*)d_in[9];
    const float* b1     = (const float*)d_in[10];
    const float* W2     = (const float*)d_in[11];
    const float* b2     = (const float*)d_in[12];
    float* out = (float*)d_out;

    float *emb, *xi, *y, *mask;
    unsigned *whh, *whl, *wembh, *wih, *w1h;
    unsigned* barsp;
    cudaGetSymbolAddress((void**)&emb,    g_emb);
    cudaGetSymbolAddress((void**)&xi,     g_xi);
    cudaGetSymbolAddress((void**)&y,      g_y);
    cudaGetSymbolAddress((void**)&mask,   g_mask);
    cudaGetSymbolAddress((void**)&whh,    g_whh);
    cudaGetSymbolAddress((void**)&whl,    g_whl);
    cudaGetSymbolAddress((void**)&wembh,  g_wembh);
    cudaGetSymbolAddress((void**)&wih,    g_wih);
    cudaGetSymbolAddress((void**)&w1h,    g_w1h);
    cudaGetSymbolAddress((void**)&barsp,  g_bars);

    // 0) barrier reset; mask; weight/state prep
    cudaMemsetAsync(barsp, 0, 8 * 32 * sizeof(unsigned));
    detect_mask_mode<<<1, 256>>>((const unsigned int*)dones);
    expand_mask<<<MM / 256, 256>>>(dones, mask);
    split_mat<<<(int)(((size_t)HH * H3) / 256), 256>>>(Wh, whh, whl, HH * H3);
    round_mat<<<(int)(((size_t)OBS * HH) / 256), 256>>>(W_emb, wembh, OBS * HH);
    round_mat<<<(int)(((size_t)HH * H3) / 256), 256>>>(Wi, wih, HH * H3);
    round_mat<<<(int)(((size_t)HH * HH) / 256), 256>>>(W1, w1h, HH * HH);
    init_h<<<(BB * HH) / 256, 256>>>(hidden, mask);

    // 1) emb = relu(WS @ W_emb + b_emb)
    {
        dim3 grid(HH / 128, MM / 128);
        mma_gemm<1><<<grid, 256>>>(ws, wembh, b_emb, emb, MM, HH, OBS);
    }
    // 2) xi = emb @ Wi + bi
    {
        dim3 grid(H3 / 128, MM / 128);
        mma_gemm<0><<<grid, 256>>>(emb, wih, bi, xi, MM, H3, HH);
    }
    // 3) GRU scan (writes y and h_out)
    {
        dim3 grid(COLG, KQ);   // 128 blocks
        gru_scan_mma<<<grid, 256>>>(mask, xi, bhn, y, out);
    }
    // 4) critic GEMM fused with value head -> g_vpart
    {
        dim3 grid(HH / 128, MM / 128);
        mma_gemm_value<<<grid, 256>>>(y, w1h, b1, W2, MM, HH, HH);
    }
    // 5) value finish -> out[131072 ..)
    value_finish<<<MM / 256, 256>>>(b2, out + (size_t)BB * HH);
}